// round 6
// baseline (speedup 1.0000x reference)
#include <cuda_runtime.h>

#define NROWS 200000
#define NNZV  3200000
#define HID   128

// ---------------- static device scratch (no runtime allocation) ----------------
__device__ int   g_cnt[NROWS];
__device__ int   g_rowptr[NROWS + 1];
__device__ int   g_cursor[NROWS];
__device__ int2  g_edge[NNZV];          // packed {col, val_bits}
__device__ float g_B0[NROWS * HID];
__device__ float g_B1[NROWS * HID];
__device__ float g_acc[NROWS * HID];
__device__ float g_w[20];
__device__ int   g_bsum[256];
__device__ int   g_is64;

// ---------------- cache-hint load/store helpers ----------------
__device__ __forceinline__ float4 ldcs4(const float4* p) {
    float4 r;
    asm volatile("ld.global.cs.v4.f32 {%0,%1,%2,%3}, [%4];"
                 : "=f"(r.x), "=f"(r.y), "=f"(r.z), "=f"(r.w) : "l"(p));
    return r;
}
__device__ __forceinline__ void stcs4(float4* p, float4 v) {
    asm volatile("st.global.cs.v4.f32 [%0], {%1,%2,%3,%4};"
                 :: "l"(p), "f"(v.x), "f"(v.y), "f"(v.z), "f"(v.w));
}

// ---------------- index dtype detection (int32 vs int64 edges) ----------------
__device__ __forceinline__ int edge_at(const void* p, int i) {
    return g_is64 ? (int)((const long long*)p)[i] : ((const int*)p)[i];
}

__global__ void detect_k(const unsigned int* p) {
    if (threadIdx.x == 0) {
        int nz = 0;
        for (int i = 1; i < 128; i += 2) nz |= (p[i] != 0u);
        g_is64 = nz ? 0 : 1;
    }
}

// ---------------- CSR build: histogram -> scan -> scatter ----------------
__global__ void hist_k(const void* rowp) {
    int i = blockIdx.x * blockDim.x + threadIdx.x;
    if (i < NNZV) atomicAdd(&g_cnt[edge_at(rowp, i)], 1);
}

__global__ void scan_local_k() {
    int t = threadIdx.x;
    int base = blockIdx.x * 1024 + t * 4;
    int v0 = (base + 0 < NROWS) ? g_cnt[base + 0] : 0;
    int v1 = (base + 1 < NROWS) ? g_cnt[base + 1] : 0;
    int v2 = (base + 2 < NROWS) ? g_cnt[base + 2] : 0;
    int v3 = (base + 3 < NROWS) ? g_cnt[base + 3] : 0;
    int tsum = v0 + v1 + v2 + v3;
    int inc = tsum;
    #pragma unroll
    for (int d = 1; d < 32; d <<= 1) {
        int u = __shfl_up_sync(0xffffffffu, inc, d);
        if ((t & 31) >= d) inc += u;
    }
    __shared__ int wsum[8], woff[8];
    if ((t & 31) == 31) wsum[t >> 5] = inc;
    __syncthreads();
    if (t == 0) {
        int s = 0;
        for (int i = 0; i < 8; i++) { woff[i] = s; s += wsum[i]; }
        g_bsum[blockIdx.x] = s;
    }
    __syncthreads();
    int ex = inc - tsum + woff[t >> 5];
    if (base + 0 < NROWS) g_rowptr[base + 0] = ex;
    if (base + 1 < NROWS) g_rowptr[base + 1] = ex + v0;
    if (base + 2 < NROWS) g_rowptr[base + 2] = ex + v0 + v1;
    if (base + 3 < NROWS) g_rowptr[base + 3] = ex + v0 + v1 + v2;
}

// parallel exclusive scan over block sums (nb <= 256) + softmax in a spare warp
__global__ void scan_bsum_k(int nb, const float* __restrict__ logits,
                            const float* __restrict__ alpha) {
    int t = threadIdx.x;
    if (t < 256) {
        int v = (t < nb) ? g_bsum[t] : 0;
        int inc = v;
        #pragma unroll
        for (int d = 1; d < 32; d <<= 1) {
            int u = __shfl_up_sync(0xffffffffu, inc, d);
            if ((t & 31) >= d) inc += u;
        }
        __shared__ int ws[8], wo[8];
        if ((t & 31) == 31) ws[t >> 5] = inc;
        __syncthreads();
        if (t == 0) {
            int s = 0;
            for (int i = 0; i < 8; i++) { wo[i] = s; s += ws[i]; }
        }
        __syncthreads();
        if (t < nb) g_bsum[t] = inc - v + wo[t >> 5];
        // warp 7's lane 0 also does softmax + alpha (independent data)
        if (t == 224) {
            float m = logits[0];
            for (int i = 1; i < 16; i++) m = fmaxf(m, logits[i]);
            float e[16], s = 0.f;
            for (int i = 0; i < 16; i++) { e[i] = __expf(logits[i] - m); s += e[i]; }
            float inv = 1.f / s;
            for (int i = 0; i < 16; i++) g_w[i] = e[i] * inv;
            g_w[16] = *alpha;
        }
    }
}

__global__ void scan_add_k() {
    int i = blockIdx.x * blockDim.x + threadIdx.x;
    if (i < NROWS) {
        int v = g_rowptr[i] + g_bsum[i >> 10];
        g_rowptr[i] = v;
        g_cursor[i] = v;
        if (i == 0) g_rowptr[NROWS] = NNZV;
    }
}

__global__ void scatter_k(const void* rowp, const void* colp, const float* __restrict__ v) {
    int i = blockIdx.x * blockDim.x + threadIdx.x;
    if (i < NNZV) {
        int r = edge_at(rowp, i);
        int p = atomicAdd(&g_cursor[r], 1);
        g_edge[p] = make_int2(edge_at(colp, i), __float_as_int(v[i]));
    }
}

// ---------------- warp-per-row SpMM gather (packed edges, 8-wide MLP) ----------------
__device__ __forceinline__ float4 spmm_row(const float4* __restrict__ src, int beg, int end, int lane) {
    float4 s0 = make_float4(0.f, 0.f, 0.f, 0.f);
    float4 s1 = make_float4(0.f, 0.f, 0.f, 0.f);
    int j = beg;
    for (; j + 8 <= end; j += 8) {
        int2 e0 = __ldg(g_edge + j + 0);
        int2 e1 = __ldg(g_edge + j + 1);
        int2 e2 = __ldg(g_edge + j + 2);
        int2 e3 = __ldg(g_edge + j + 3);
        int2 e4 = __ldg(g_edge + j + 4);
        int2 e5 = __ldg(g_edge + j + 5);
        int2 e6 = __ldg(g_edge + j + 6);
        int2 e7 = __ldg(g_edge + j + 7);
        float4 a0 = __ldg(src + e0.x * 32 + lane);
        float4 a1 = __ldg(src + e1.x * 32 + lane);
        float4 a2 = __ldg(src + e2.x * 32 + lane);
        float4 a3 = __ldg(src + e3.x * 32 + lane);
        float4 a4 = __ldg(src + e4.x * 32 + lane);
        float4 a5 = __ldg(src + e5.x * 32 + lane);
        float4 a6 = __ldg(src + e6.x * 32 + lane);
        float4 a7 = __ldg(src + e7.x * 32 + lane);
        float v0 = __int_as_float(e0.y), v1 = __int_as_float(e1.y);
        float v2 = __int_as_float(e2.y), v3 = __int_as_float(e3.y);
        float v4 = __int_as_float(e4.y), v5 = __int_as_float(e5.y);
        float v6 = __int_as_float(e6.y), v7 = __int_as_float(e7.y);
        s0.x = fmaf(v0, a0.x, s0.x); s0.y = fmaf(v0, a0.y, s0.y);
        s0.z = fmaf(v0, a0.z, s0.z); s0.w = fmaf(v0, a0.w, s0.w);
        s1.x = fmaf(v1, a1.x, s1.x); s1.y = fmaf(v1, a1.y, s1.y);
        s1.z = fmaf(v1, a1.z, s1.z); s1.w = fmaf(v1, a1.w, s1.w);
        s0.x = fmaf(v2, a2.x, s0.x); s0.y = fmaf(v2, a2.y, s0.y);
        s0.z = fmaf(v2, a2.z, s0.z); s0.w = fmaf(v2, a2.w, s0.w);
        s1.x = fmaf(v3, a3.x, s1.x); s1.y = fmaf(v3, a3.y, s1.y);
        s1.z = fmaf(v3, a3.z, s1.z); s1.w = fmaf(v3, a3.w, s1.w);
        s0.x = fmaf(v4, a4.x, s0.x); s0.y = fmaf(v4, a4.y, s0.y);
        s0.z = fmaf(v4, a4.z, s0.z); s0.w = fmaf(v4, a4.w, s0.w);
        s1.x = fmaf(v5, a5.x, s1.x); s1.y = fmaf(v5, a5.y, s1.y);
        s1.z = fmaf(v5, a5.z, s1.z); s1.w = fmaf(v5, a5.w, s1.w);
        s0.x = fmaf(v6, a6.x, s0.x); s0.y = fmaf(v6, a6.y, s0.y);
        s0.z = fmaf(v6, a6.z, s0.z); s0.w = fmaf(v6, a6.w, s0.w);
        s1.x = fmaf(v7, a7.x, s1.x); s1.y = fmaf(v7, a7.y, s1.y);
        s1.z = fmaf(v7, a7.z, s1.z); s1.w = fmaf(v7, a7.w, s1.w);
    }
    for (; j < end; ++j) {
        int2 e = __ldg(g_edge + j);
        float v = __int_as_float(e.y);
        float4 a = __ldg(src + e.x * 32 + lane);
        s0.x = fmaf(v, a.x, s0.x); s0.y = fmaf(v, a.y, s0.y);
        s0.z = fmaf(v, a.z, s0.z); s0.w = fmaf(v, a.w, s0.w);
    }
    s0.x += s1.x; s0.y += s1.y; s0.z += s1.z; s0.w += s1.w;
    return s0;
}

// k = 1: s = spmm(x); T1 = s - x; acc = (w0 - w1 - alpha)*x + (w1 + alpha/2)*s
__global__ void __launch_bounds__(256) cheb_first_k(const float* __restrict__ x) {
    int w = (blockIdx.x * blockDim.x + threadIdx.x) >> 5;
    if (w >= NROWS) return;
    int lane = threadIdx.x & 31;
    float4 s = spmm_row((const float4*)x, g_rowptr[w], g_rowptr[w + 1], lane);
    int idx = w * 32 + lane;
    float4 xr = __ldg((const float4*)x + idx);
    float w0 = g_w[0], w1 = g_w[1], al = g_w[16];
    float ca = w0 - w1 - al, cb = w1 + 0.5f * al;
    float4 t1, a;
    t1.x = s.x - xr.x; t1.y = s.y - xr.y; t1.z = s.z - xr.z; t1.w = s.w - xr.w;
    a.x = fmaf(ca, xr.x, cb * s.x); a.y = fmaf(ca, xr.y, cb * s.y);
    a.z = fmaf(ca, xr.z, cb * s.z); a.w = fmaf(ca, xr.w, cb * s.w);
    ((float4*)g_B0)[idx] = t1;
    stcs4((float4*)g_acc + idx, a);
}

// Step producing T_m:  Tn = 2*spmm(Tcur) - 2*Tcur - Tprev
// mode 0: plain; mode 1: tri-acc (acc += w[m-2]*Tp + w[m-1]*Tc + w[m]*Tn);
// mode 2: last (out = -(acc + w[m-1]*Tc + w[m]*Tn))
__global__ void __launch_bounds__(256) cheb_step_k(const float* __restrict__ Tcur,
                                                   const float* Tprev, float* Tnew,
                                                   float* __restrict__ out, int m, int mode) {
    int w = (blockIdx.x * blockDim.x + threadIdx.x) >> 5;
    if (w >= NROWS) return;
    int lane = threadIdx.x & 31;
    float4 s = spmm_row((const float4*)Tcur, g_rowptr[w], g_rowptr[w + 1], lane);
    int idx = w * 32 + lane;
    float4 tc = __ldg((const float4*)Tcur + idx);
    float4 tp = ldcs4((const float4*)Tprev + idx);   // dead after read (buffer reused as Tnew)
    float4 tn;
    tn.x = 2.f * s.x - 2.f * tc.x - tp.x;
    tn.y = 2.f * s.y - 2.f * tc.y - tp.y;
    tn.z = 2.f * s.z - 2.f * tc.z - tp.z;
    tn.w = 2.f * s.w - 2.f * tc.w - tp.w;
    if (mode == 0) {
        ((float4*)Tnew)[idx] = tn;
    } else if (mode == 1) {
        ((float4*)Tnew)[idx] = tn;
        float wa = g_w[m - 2], wb = g_w[m - 1], wc = g_w[m];
        float4 a = ldcs4((const float4*)g_acc + idx);
        a.x = fmaf(wa, tp.x, fmaf(wb, tc.x, fmaf(wc, tn.x, a.x)));
        a.y = fmaf(wa, tp.y, fmaf(wb, tc.y, fmaf(wc, tn.y, a.y)));
        a.z = fmaf(wa, tp.z, fmaf(wb, tc.z, fmaf(wc, tn.z, a.z)));
        a.w = fmaf(wa, tp.w, fmaf(wb, tc.w, fmaf(wc, tn.w, a.w)));
        stcs4((float4*)g_acc + idx, a);
    } else {
        float wb = g_w[m - 1], wc = g_w[m];
        float4 a = ldcs4((const float4*)g_acc + idx);
        float4 o;
        o.x = -fmaf(wb, tc.x, fmaf(wc, tn.x, a.x));
        o.y = -fmaf(wb, tc.y, fmaf(wc, tn.y, a.y));
        o.z = -fmaf(wb, tc.z, fmaf(wc, tn.z, a.z));
        o.w = -fmaf(wb, tc.w, fmaf(wc, tn.w, a.w));
        stcs4((float4*)out + idx, o);
    }
}

// ---------------- host ----------------
extern "C" void kernel_launch(void* const* d_in, const int* in_sizes, int n_in,
                              void* d_out, int out_size) {
    const float* x      = (const float*)d_in[0];
    const float* vals   = (const float*)d_in[1];
    const float* logits = (const float*)d_in[2];
    const float* alpha  = (const float*)d_in[3];
    const void*  erow   = d_in[4];
    const void*  ecol   = d_in[5];
    float* out = (float*)d_out;
    (void)in_sizes; (void)n_in; (void)out_size;

    void *cntp, *b0p, *b1p;
    cudaGetSymbolAddress(&cntp, g_cnt);
    cudaGetSymbolAddress(&b0p, g_B0);
    cudaGetSymbolAddress(&b1p, g_B1);

    cudaMemsetAsync(cntp, 0, NROWS * sizeof(int), 0);
    detect_k<<<1, 32>>>((const unsigned int*)erow);
    hist_k<<<(NNZV + 255) / 256, 256>>>(erow);
    int nb = (NROWS + 1023) / 1024;
    scan_local_k<<<nb, 256>>>();
    scan_bsum_k<<<1, 256>>>(nb, logits, alpha);
    scan_add_k<<<(NROWS + 255) / 256, 256>>>();
    scatter_k<<<(NNZV + 255) / 256, 256>>>(erow, ecol, vals);

    int grid = (NROWS * 32 + 255) / 256;
    cheb_first_k<<<grid, 256>>>(x);

    const float* Tprev = x;
    float* Tcur = (float*)b0p;
    float* Bother = (float*)b1p;
    for (int m = 2; m <= 15; ++m) {
        int mode;
        if (m == 15) mode = 2;                                     // last: fold w14,w15, write out
        else if (m == 4 || m == 7 || m == 10 || m == 13) mode = 1; // tri-acc
        else mode = 0;
        float* Tnew = (m == 2) ? Bother : (float*)Tprev;  // overwrite T_{m-2} (row-local safe)
        cheb_step_k<<<grid, 256>>>(Tcur, Tprev, Tnew, out, m, mode);
        Tprev = Tcur;
        Tcur = Tnew;
    }
}

// round 7
// speedup vs baseline: 1.2198x; 1.2198x over previous
#include <cuda_runtime.h>

#define NROWS 200000
#define NNZV  3200000
#define HID   128
#define HALF  64
#define NWARPS (NROWS / 2)   // two rows per warp

// ---------------- static device scratch (no runtime allocation) ----------------
__device__ int   g_cnt[NROWS];
__device__ int   g_rowptr[NROWS + 1];
__device__ int   g_cursor[NROWS];
__device__ int2  g_edge[NNZV];          // packed {col, val_bits}
__device__ float g_B0[NROWS * HID];
__device__ float g_B1[NROWS * HID];
__device__ float g_acc[NROWS * HID];
__device__ float g_w[20];
__device__ int   g_bsum[256];
__device__ int   g_is64;

// ---------------- cache-hint load/store helpers ----------------
__device__ __forceinline__ float4 ldcs4(const float4* p) {
    float4 r;
    asm volatile("ld.global.cs.v4.f32 {%0,%1,%2,%3}, [%4];"
                 : "=f"(r.x), "=f"(r.y), "=f"(r.z), "=f"(r.w) : "l"(p));
    return r;
}
__device__ __forceinline__ void stcs4(float4* p, float4 v) {
    asm volatile("st.global.cs.v4.f32 [%0], {%1,%2,%3,%4};"
                 :: "l"(p), "f"(v.x), "f"(v.y), "f"(v.z), "f"(v.w));
}

// ---------------- index dtype detection (int32 vs int64 edges) ----------------
__device__ __forceinline__ int edge_at(const void* p, int i) {
    return g_is64 ? (int)((const long long*)p)[i] : ((const int*)p)[i];
}

__global__ void detect_k(const unsigned int* p) {
    if (threadIdx.x == 0) {
        int nz = 0;
        for (int i = 1; i < 128; i += 2) nz |= (p[i] != 0u);
        g_is64 = nz ? 0 : 1;
    }
}

// ---------------- CSR build: histogram -> scan -> scatter ----------------
__global__ void hist_k(const void* rowp) {
    int i = blockIdx.x * blockDim.x + threadIdx.x;
    if (i < NNZV) atomicAdd(&g_cnt[edge_at(rowp, i)], 1);
}

__global__ void scan_local_k() {
    int t = threadIdx.x;
    int base = blockIdx.x * 1024 + t * 4;
    int v0 = (base + 0 < NROWS) ? g_cnt[base + 0] : 0;
    int v1 = (base + 1 < NROWS) ? g_cnt[base + 1] : 0;
    int v2 = (base + 2 < NROWS) ? g_cnt[base + 2] : 0;
    int v3 = (base + 3 < NROWS) ? g_cnt[base + 3] : 0;
    int tsum = v0 + v1 + v2 + v3;
    int inc = tsum;
    #pragma unroll
    for (int d = 1; d < 32; d <<= 1) {
        int u = __shfl_up_sync(0xffffffffu, inc, d);
        if ((t & 31) >= d) inc += u;
    }
    __shared__ int wsum[8], woff[8];
    if ((t & 31) == 31) wsum[t >> 5] = inc;
    __syncthreads();
    if (t == 0) {
        int s = 0;
        for (int i = 0; i < 8; i++) { woff[i] = s; s += wsum[i]; }
        g_bsum[blockIdx.x] = s;
    }
    __syncthreads();
    int ex = inc - tsum + woff[t >> 5];
    if (base + 0 < NROWS) g_rowptr[base + 0] = ex;
    if (base + 1 < NROWS) g_rowptr[base + 1] = ex + v0;
    if (base + 2 < NROWS) g_rowptr[base + 2] = ex + v0 + v1;
    if (base + 3 < NROWS) g_rowptr[base + 3] = ex + v0 + v1 + v2;
}

// parallel exclusive scan over block sums (nb <= 256) + softmax in a spare warp
__global__ void scan_bsum_k(int nb, const float* __restrict__ logits,
                            const float* __restrict__ alpha) {
    int t = threadIdx.x;
    int v = (t < nb) ? g_bsum[t] : 0;
    int inc = v;
    #pragma unroll
    for (int d = 1; d < 32; d <<= 1) {
        int u = __shfl_up_sync(0xffffffffu, inc, d);
        if ((t & 31) >= d) inc += u;
    }
    __shared__ int ws[8], wo[8];
    if ((t & 31) == 31) ws[t >> 5] = inc;
    __syncthreads();
    if (t == 0) {
        int s = 0;
        for (int i = 0; i < 8; i++) { wo[i] = s; s += ws[i]; }
    }
    __syncthreads();
    if (t < nb) g_bsum[t] = inc - v + wo[t >> 5];
    if (t == 224) {
        float m = logits[0];
        for (int i = 1; i < 16; i++) m = fmaxf(m, logits[i]);
        float e[16], s = 0.f;
        for (int i = 0; i < 16; i++) { e[i] = __expf(logits[i] - m); s += e[i]; }
        float inv = 1.f / s;
        for (int i = 0; i < 16; i++) g_w[i] = e[i] * inv;
        g_w[16] = *alpha;
    }
}

__global__ void scan_add_k() {
    int i = blockIdx.x * blockDim.x + threadIdx.x;
    if (i < NROWS) {
        int v = g_rowptr[i] + g_bsum[i >> 10];
        g_rowptr[i] = v;
        g_cursor[i] = v;
        if (i == 0) g_rowptr[NROWS] = NNZV;
    }
}

__global__ void scatter_k(const void* rowp, const void* colp, const float* __restrict__ v) {
    int i = blockIdx.x * blockDim.x + threadIdx.x;
    if (i < NNZV) {
        int r = edge_at(rowp, i);
        int p = atomicAdd(&g_cursor[r], 1);
        g_edge[p] = make_int2(edge_at(colp, i), __float_as_int(v[i]));
    }
}

// ---------------- half-warp-per-row, half-width SpMM gather ----------------
// Each half-warp (16 lanes) owns one row; lane16 holds float4 -> 16x16B = 256B = one half-row.
// srcf = buffer base; gather address = srcf + col*HID + hoff + lane16*4.
__device__ __forceinline__ float4 spmm_half(const float* __restrict__ srcf, int hoff,
                                            int beg, int end, int lane16) {
    float4 s = make_float4(0.f, 0.f, 0.f, 0.f);
    #pragma unroll 4
    for (int j = beg; j < end; ++j) {
        int2 e = __ldg(g_edge + j);
        float v = __int_as_float(e.y);
        const float4* p = (const float4*)(srcf + e.x * HID + hoff) + lane16;
        float4 a = __ldg(p);
        s.x = fmaf(v, a.x, s.x); s.y = fmaf(v, a.y, s.y);
        s.z = fmaf(v, a.z, s.z); s.w = fmaf(v, a.w, s.w);
    }
    return s;
}

// m = 1 (per half): s = spmm(x); T1 = s - x; acc = (w0-w1-alpha)*x + (w1+alpha/2)*s
__global__ void __launch_bounds__(256) cheb_first_h(const float* __restrict__ x, int hoff) {
    int gw = (blockIdx.x * blockDim.x + threadIdx.x) >> 5;
    if (gw >= NWARPS) return;
    int lane = threadIdx.x & 31;
    int row = 2 * gw + (lane >> 4);
    int lane16 = lane & 15;
    float4 s = spmm_half(x, hoff, g_rowptr[row], g_rowptr[row + 1], lane16);
    size_t off = (size_t)row * HID + hoff;
    float4 xr = __ldg((const float4*)(x + off) + lane16);
    float w0 = g_w[0], w1 = g_w[1], al = g_w[16];
    float ca = w0 - w1 - al, cb = w1 + 0.5f * al;
    float4 t1, a;
    t1.x = s.x - xr.x; t1.y = s.y - xr.y; t1.z = s.z - xr.z; t1.w = s.w - xr.w;
    a.x = fmaf(ca, xr.x, cb * s.x); a.y = fmaf(ca, xr.y, cb * s.y);
    a.z = fmaf(ca, xr.z, cb * s.z); a.w = fmaf(ca, xr.w, cb * s.w);
    ((float4*)(g_B0 + off))[lane16] = t1;
    stcs4((float4*)(g_acc + off) + lane16, a);
}

// Step producing T_m on half hoff: Tn = 2*spmm(Tcur) - 2*Tcur - Tprev
// mode 0: plain; mode 1: tri-acc (acc += w[m-2]*Tp + w[m-1]*Tc + w[m]*Tn);
// mode 2: last (out = -(acc + w[m-1]*Tc + w[m]*Tn))
__global__ void __launch_bounds__(256) cheb_step_h(const float* __restrict__ Tcur,
                                                   const float* Tprev, float* Tnew,
                                                   float* __restrict__ out,
                                                   int hoff, int m, int mode) {
    int gw = (blockIdx.x * blockDim.x + threadIdx.x) >> 5;
    if (gw >= NWARPS) return;
    int lane = threadIdx.x & 31;
    int row = 2 * gw + (lane >> 4);
    int lane16 = lane & 15;
    float4 s = spmm_half(Tcur, hoff, g_rowptr[row], g_rowptr[row + 1], lane16);
    size_t off = (size_t)row * HID + hoff;
    float4 tc = __ldg((const float4*)(Tcur + off) + lane16);
    float4 tp = ldcs4((const float4*)(Tprev + off) + lane16);  // dead after read (buffer reused as Tnew)
    float4 tn;
    tn.x = 2.f * s.x - 2.f * tc.x - tp.x;
    tn.y = 2.f * s.y - 2.f * tc.y - tp.y;
    tn.z = 2.f * s.z - 2.f * tc.z - tp.z;
    tn.w = 2.f * s.w - 2.f * tc.w - tp.w;
    if (mode == 0) {
        ((float4*)(Tnew + off))[lane16] = tn;
    } else if (mode == 1) {
        ((float4*)(Tnew + off))[lane16] = tn;
        float wa = g_w[m - 2], wb = g_w[m - 1], wc = g_w[m];
        float4 a = ldcs4((const float4*)(g_acc + off) + lane16);
        a.x = fmaf(wa, tp.x, fmaf(wb, tc.x, fmaf(wc, tn.x, a.x)));
        a.y = fmaf(wa, tp.y, fmaf(wb, tc.y, fmaf(wc, tn.y, a.y)));
        a.z = fmaf(wa, tp.z, fmaf(wb, tc.z, fmaf(wc, tn.z, a.z)));
        a.w = fmaf(wa, tp.w, fmaf(wb, tc.w, fmaf(wc, tn.w, a.w)));
        stcs4((float4*)(g_acc + off) + lane16, a);
    } else {
        float wb = g_w[m - 1], wc = g_w[m];
        float4 a = ldcs4((const float4*)(g_acc + off) + lane16);
        float4 o;
        o.x = -fmaf(wb, tc.x, fmaf(wc, tn.x, a.x));
        o.y = -fmaf(wb, tc.y, fmaf(wc, tn.y, a.y));
        o.z = -fmaf(wb, tc.z, fmaf(wc, tn.z, a.z));
        o.w = -fmaf(wb, tc.w, fmaf(wc, tn.w, a.w));
        stcs4((float4*)(out + off) + lane16, o);
    }
}

// ---------------- host ----------------
extern "C" void kernel_launch(void* const* d_in, const int* in_sizes, int n_in,
                              void* d_out, int out_size) {
    const float* x      = (const float*)d_in[0];
    const float* vals   = (const float*)d_in[1];
    const float* logits = (const float*)d_in[2];
    const float* alpha  = (const float*)d_in[3];
    const void*  erow   = d_in[4];
    const void*  ecol   = d_in[5];
    float* out = (float*)d_out;
    (void)in_sizes; (void)n_in; (void)out_size;

    void *cntp, *b0p, *b1p;
    cudaGetSymbolAddress(&cntp, g_cnt);
    cudaGetSymbolAddress(&b0p, g_B0);
    cudaGetSymbolAddress(&b1p, g_B1);

    cudaMemsetAsync(cntp, 0, NROWS * sizeof(int), 0);
    detect_k<<<1, 32>>>((const unsigned int*)erow);
    hist_k<<<(NNZV + 255) / 256, 256>>>(erow);
    int nb = (NROWS + 1023) / 1024;
    scan_local_k<<<nb, 256>>>();
    scan_bsum_k<<<1, 256>>>(nb, logits, alpha);
    scan_add_k<<<(NROWS + 255) / 256, 256>>>();
    scatter_k<<<(NNZV + 255) / 256, 256>>>(erow, ecol, vals);

    int grid = (NWARPS * 32 + 255) / 256;   // 12500 blocks

    for (int h = 0; h < 2; ++h) {
        int hoff = h * HALF;
        cheb_first_h<<<grid, 256>>>(x, hoff);
        const float* Tprev = x;
        float* Tcur = (float*)b0p;
        float* Bother = (float*)b1p;
        for (int m = 2; m <= 15; ++m) {
            int mode;
            if (m == 15) mode = 2;                                     // last: fold w14,w15, write out
            else if (m == 4 || m == 7 || m == 10 || m == 13) mode = 1; // tri-acc
            else mode = 0;
            float* Tnew = (m == 2) ? Bother : (float*)Tprev;  // overwrite T_{m-2} (row-local safe)
            cheb_step_h<<<grid, 256>>>(Tcur, Tprev, Tnew, out, hoff, m, mode);
            Tprev = Tcur;
            Tcur = Tnew;
        }
    }
}